// round 1
// baseline (speedup 1.0000x reference)
#include <cuda_runtime.h>
#include <cuda_bf16.h>
#include <stdint.h>

// Problem constants (fixed by the reference)
#define BB 4096
#define VV 64
#define FF 128

// out layout (float32): [ softmax B*V*F | cond_adj B*V*F | ent B ]
__global__ void __launch_bounds__(FF) adj_gen_kernel(
    const float* __restrict__ S,    // softmax  [B,V,F]
    const float* __restrict__ LP,   // log_probs[B,V,F]
    float* __restrict__ out)
{
    const int b = blockIdx.x;
    const int f = threadIdx.x;  // 0..127, one factor per thread

    const size_t base = (size_t)b * (VV * FF) + f;
    const float* __restrict__ sp  = S  + base;
    const float* __restrict__ lpp = LP + base;
    float* __restrict__ outS = out + base;
    float* __restrict__ outC = out + (size_t)BB * VV * FF + base;

    float v0 = -1e30f, v1 = -1e30f, v2 = -1e30f;
    int   i0 = 0,      i1 = 0,      i2 = 0;
    unsigned long long thresh = 0ull;
    float ent_acc = 0.0f;

#pragma unroll
    for (int v = 0; v < VV; ++v) {
        const size_t off = (size_t)v * FF;
        float s  = sp[off];
        float lp = lpp[off];
        outS[off] = s;                       // pass-through copy of softmax
        ent_acc = fmaf(s, lp, ent_acc);      // sum s*log s
        if (s > 0.01f) thresh |= (1ull << v);
        // top-3 insert; strict > keeps earlier index on ties (== lax.top_k)
        if (s > v0)      { v2 = v1; i2 = i1; v1 = v0; i1 = i0; v0 = s; i0 = v; }
        else if (s > v1) { v2 = v1; i2 = i1; v1 = s;  i1 = v; }
        else if (s > v2) { v2 = s;  i2 = v; }
    }

    // Order-selection logic (matches reference exactly)
    float p3 = v0 * v0 * v0;
    float p2 = 3.0f * v1 * v2 * (v1 + v2);
    float p1 = 6.0f * v0 * v1 * v2;
    bool c3 = (p3 > p2) && (p3 > p1);
    bool c2 = (p2 >= p3) && (p2 > p1);
    int j1 = c3 ? i0 : i1;
    int j2 = (c3 || c2) ? i0 : i2;

    unsigned long long sel = (1ull << i0) | (1ull << j1) | (1ull << j2);
    unsigned long long m   = thresh & sel;

    // Write-only second pass for cond_adj (no re-read of softmax)
#pragma unroll
    for (int v = 0; v < VV; ++v) {
        outC[(size_t)v * FF] = ((m >> v) & 1ull) ? 1.0f : 0.0f;
    }

    // Block-reduce entropy over the 128 factor-threads
    __shared__ float sred[4];
#pragma unroll
    for (int offv = 16; offv > 0; offv >>= 1)
        ent_acc += __shfl_down_sync(0xffffffffu, ent_acc, offv);
    if ((threadIdx.x & 31) == 0) sred[threadIdx.x >> 5] = ent_acc;
    __syncthreads();
    if (threadIdx.x == 0) {
        float tot = sred[0] + sred[1] + sred[2] + sred[3];
        out[(size_t)2 * BB * VV * FF + b] = -tot / (float)FF;
    }
}

extern "C" void kernel_launch(void* const* d_in, const int* in_sizes, int n_in,
                              void* d_out, int out_size)
{
    const float* softmax   = (const float*)d_in[0];
    const float* log_probs = (const float*)d_in[1];
    float* out = (float*)d_out;
    adj_gen_kernel<<<BB, FF>>>(softmax, log_probs, out);
}

// round 2
// speedup vs baseline: 1.0994x; 1.0994x over previous
#include <cuda_runtime.h>
#include <cuda_bf16.h>
#include <stdint.h>

#define BB 4096
#define VV 64
#define FF 128

// FFMA-only logf (Cephes-style). Valid for normal positive x; softmax outputs
// are in (0,1) and well away from denormals. ~1 ulp-level accuracy, no MUFU.
__device__ __forceinline__ float fast_logf(float x) {
    int xi = __float_as_int(x);
    int e  = (xi - 0x3f3504f3) >> 23;                 // center at sqrt(1/2)
    float m = __int_as_float(xi - (e << 23));         // m in [0.7071, 1.4142)
    float f = m - 1.0f;
    float z = f * f;
    float p =            7.0376836292e-2f;
    p = fmaf(p, f, -1.1514610310e-1f);
    p = fmaf(p, f,  1.1676998740e-1f);
    p = fmaf(p, f, -1.2420140846e-1f);
    p = fmaf(p, f,  1.4249322787e-1f);
    p = fmaf(p, f, -1.6668057665e-1f);
    p = fmaf(p, f,  2.0000714765e-1f);
    p = fmaf(p, f, -2.4999993993e-1f);
    p = fmaf(p, f,  3.3333331174e-1f);
    p = p * f * z;                                    // f^3 * P(f)
    p = fmaf(-0.5f, z, p);
    return fmaf((float)e, 0.693147180559945f, f + p);
}

// One warp per batch. Lane l owns factors 4l..4l+3 (one float4 column).
// out layout (float32): [ softmax B*V*F | cond_adj B*V*F | ent B ]
__global__ void __launch_bounds__(128) adj_gen_kernel(
    const float4* __restrict__ S,     // softmax [B,V,F] as float4
    float* __restrict__ out)
{
    const int warp = threadIdx.x >> 5;
    const int lane = threadIdx.x & 31;
    const int b    = blockIdx.x * 4 + warp;

    const size_t baseq = (size_t)b * (VV * FF / 4) + lane;   // float4 units
    const float4* __restrict__ sp   = S + baseq;
    float4* __restrict__ outS = reinterpret_cast<float4*>(out) + baseq;
    float4* __restrict__ outC = reinterpret_cast<float4*>(out)
                                + (size_t)BB * VV * FF / 4 + baseq;

    float v0[4], v1[4], v2[4];
    int   i0[4], i1[4], i2[4];
    unsigned long long th[4];
#pragma unroll
    for (int j = 0; j < 4; ++j) {
        v0[j] = v1[j] = v2[j] = -1e30f;
        i0[j] = i1[j] = i2[j] = 0;
        th[j] = 0ull;
    }
    float ent = 0.0f;

#pragma unroll 4
    for (int v = 0; v < VV; ++v) {
        float4 s4 = __ldcs(&sp[(size_t)v * (FF / 4)]);
        __stcs(&outS[(size_t)v * (FF / 4)], s4);
        float sv[4] = {s4.x, s4.y, s4.z, s4.w};
#pragma unroll
        for (int j = 0; j < 4; ++j) {
            float s = sv[j];
            ent = fmaf(s, fast_logf(s), ent);
            th[j] |= (unsigned long long)(s > 0.01f) << v;
            // branchless top-3 insert; strict > keeps earlier index on ties
            bool g0 = s > v0[j], g1 = s > v1[j], g2 = s > v2[j];
            v2[j] = g1 ? v1[j] : (g2 ? s : v2[j]);
            i2[j] = g1 ? i1[j] : (g2 ? v : i2[j]);
            v1[j] = g0 ? v0[j] : (g1 ? s : v1[j]);
            i1[j] = g0 ? i0[j] : (g1 ? v : i1[j]);
            v0[j] = g0 ? s : v0[j];
            i0[j] = g0 ? v : i0[j];
        }
    }

    // Order selection (matches reference) -> selected-index bitmask per factor
    unsigned long long m[4];
#pragma unroll
    for (int j = 0; j < 4; ++j) {
        float p3 = v0[j] * v0[j] * v0[j];
        float p2 = 3.0f * v1[j] * v2[j] * (v1[j] + v2[j]);
        float p1 = 6.0f * v0[j] * v1[j] * v2[j];
        bool c3 = (p3 > p2) && (p3 > p1);
        bool c2 = (p2 >= p3) && (p2 > p1);
        int j1 = c3 ? i0[j] : i1[j];
        int j2 = (c3 || c2) ? i0[j] : i2[j];
        unsigned long long sel =
            (1ull << i0[j]) | (1ull << j1) | (1ull << j2);
        m[j] = th[j] & sel;
    }

    // Write-only pass for cond_adj
#pragma unroll 4
    for (int v = 0; v < VV; ++v) {
        float4 c;
        c.x = (m[0] >> v) & 1ull ? 1.0f : 0.0f;
        c.y = (m[1] >> v) & 1ull ? 1.0f : 0.0f;
        c.z = (m[2] >> v) & 1ull ? 1.0f : 0.0f;
        c.w = (m[3] >> v) & 1ull ? 1.0f : 0.0f;
        __stcs(&outC[(size_t)v * (FF / 4)], c);
    }

    // Warp-level entropy reduction (one warp == one batch)
#pragma unroll
    for (int off = 16; off > 0; off >>= 1)
        ent += __shfl_xor_sync(0xffffffffu, ent, off);
    if (lane == 0)
        out[(size_t)2 * BB * VV * FF + b] = -ent / (float)FF;
}

extern "C" void kernel_launch(void* const* d_in, const int* in_sizes, int n_in,
                              void* d_out, int out_size)
{
    const float4* softmax = (const float4*)d_in[0];
    // d_in[1] (log_probs) intentionally unread: recomputed as log(softmax)
    float* out = (float*)d_out;
    adj_gen_kernel<<<BB / 4, 128>>>(softmax, out);
}